// round 1
// baseline (speedup 1.0000x reference)
#include <cuda_runtime.h>
#include <math.h>

#define BB   4
#define CC   384
#define HH   56
#define WW   56
#define HWW  3136          // H*W
#define NTOK 12544         // B*H*W
#define GG   12
#define GCH  32
#define KK2  9             // KS*KS
#define OMC  324           // G*K*3
#define HID  1536
#define EPSV 1e-5f

// ---------------- scratch (device globals; no allocation) ----------------
__device__ float g_xp [NTOK * CC];   // transposed input (N,C)
__device__ float g_tn [NTOK * CC];   // ln1 output
__device__ float g_val[NTOK * CC];   // v projection
__device__ float g_om [NTOK * OMC];  // offsets + masks
__device__ float g_dcn[NTOK * CC];   // dcn sampled output
__device__ float g_res[NTOK * CC];   // xp + oproj(dcn)
__device__ float g_ln2[NTOK * CC];   // ln2 output
__device__ float g_hid[NTOK * HID];  // fc1+gelu
__device__ float g_fin[NTOK * CC];   // res + fc2 out

// ---------------- LN1: read x (B,C,H,W) transposed, write xp & tn --------
__global__ void ln1_kernel(const float* __restrict__ x,
                           const float* __restrict__ gam,
                           const float* __restrict__ bet,
                           float* __restrict__ xp, float* __restrict__ tn)
{
    int warp = (blockIdx.x * blockDim.x + threadIdx.x) >> 5;
    if (warp >= NTOK) return;
    int lane = threadIdx.x & 31;
    int b  = warp / HWW;
    int hw = warp % HWW;
    const float* xb = x + (size_t)b * CC * HWW + hw;

    float v[12];
#pragma unroll
    for (int i = 0; i < 12; i++) v[i] = xb[(size_t)(lane + 32 * i) * HWW];

    float s = 0.f;
#pragma unroll
    for (int i = 0; i < 12; i++) s += v[i];
#pragma unroll
    for (int o = 16; o; o >>= 1) s += __shfl_xor_sync(0xffffffffu, s, o);
    float mu = s * (1.0f / CC);

    float q = 0.f;
#pragma unroll
    for (int i = 0; i < 12; i++) { float d = v[i] - mu; q += d * d; }
#pragma unroll
    for (int o = 16; o; o >>= 1) q += __shfl_xor_sync(0xffffffffu, q, o);
    float rs = rsqrtf(q * (1.0f / CC) + EPSV);

    size_t base = (size_t)warp * CC;
#pragma unroll
    for (int i = 0; i < 12; i++) {
        int c = lane + 32 * i;
        xp[base + c] = v[i];
        tn[base + c] = (v[i] - mu) * rs * gam[c] + bet[c];
    }
}

// ---------------- LN2: coalesced read of res (N,C) -----------------------
__global__ void ln2_kernel(const float* __restrict__ res,
                           const float* __restrict__ gam,
                           const float* __restrict__ bet,
                           float* __restrict__ outp)
{
    int warp = (blockIdx.x * blockDim.x + threadIdx.x) >> 5;
    if (warp >= NTOK) return;
    int lane = threadIdx.x & 31;
    size_t base = (size_t)warp * CC;

    float v[12];
#pragma unroll
    for (int i = 0; i < 12; i++) v[i] = res[base + lane + 32 * i];

    float s = 0.f;
#pragma unroll
    for (int i = 0; i < 12; i++) s += v[i];
#pragma unroll
    for (int o = 16; o; o >>= 1) s += __shfl_xor_sync(0xffffffffu, s, o);
    float mu = s * (1.0f / CC);

    float q = 0.f;
#pragma unroll
    for (int i = 0; i < 12; i++) { float d = v[i] - mu; q += d * d; }
#pragma unroll
    for (int o = 16; o; o >>= 1) q += __shfl_xor_sync(0xffffffffu, q, o);
    float rs = rsqrtf(q * (1.0f / CC) + EPSV);

#pragma unroll
    for (int i = 0; i < 12; i++) {
        int c = lane + 32 * i;
        outp[base + c] = (v[i] - mu) * rs * gam[c] + bet[c];
    }
}

// ---------------- tiled fp32 GEMM with fused epilogues --------------------
// Out[M,Nn] = A[M,K] @ Wm[K,Nn]   (all row-major)
// EPI: 0 = +bias ; 1 = +bias then exact GELU ; 2 = +bias + Add[M,Nn]
template <int EPI>
__global__ void gemm_k(const float* __restrict__ A,
                       const float* __restrict__ Wm,
                       const float* __restrict__ bias,
                       const float* __restrict__ Add,
                       float* __restrict__ Out,
                       int M, int Nn, int K)
{
    __shared__ float As[16][68];   // padded so float4 rows stay 16B aligned
    __shared__ float Bs[16][64];

    int m0 = blockIdx.x * 64;
    int n0 = blockIdx.y * 64;
    int t  = threadIdx.x;          // 256 threads
    int tx = t & 15;
    int ty = t >> 4;

    float acc[4][4];
#pragma unroll
    for (int i = 0; i < 4; i++)
#pragma unroll
        for (int j = 0; j < 4; j++) acc[i][j] = 0.f;

    for (int k0 = 0; k0 < K; k0 += 16) {
#pragma unroll
        for (int i = 0; i < 4; i++) {
            int e = t + 256 * i;
            int r = e >> 4, c = e & 15;
            As[c][r] = A[(size_t)(m0 + r) * K + k0 + c];
        }
#pragma unroll
        for (int i = 0; i < 4; i++) {
            int e = t + 256 * i;
            int r = e >> 6, c = e & 63;
            int n = n0 + c;
            Bs[r][c] = (n < Nn) ? Wm[(size_t)(k0 + r) * Nn + n] : 0.f;
        }
        __syncthreads();

#pragma unroll
        for (int k = 0; k < 16; k++) {
            float4 a4 = *reinterpret_cast<const float4*>(&As[k][ty * 4]);
            float4 b4 = *reinterpret_cast<const float4*>(&Bs[k][tx * 4]);
            float a[4] = {a4.x, a4.y, a4.z, a4.w};
            float bv[4] = {b4.x, b4.y, b4.z, b4.w};
#pragma unroll
            for (int i = 0; i < 4; i++)
#pragma unroll
                for (int j = 0; j < 4; j++) acc[i][j] += a[i] * bv[j];
        }
        __syncthreads();
    }

#pragma unroll
    for (int i = 0; i < 4; i++) {
        int m = m0 + ty * 4 + i;
#pragma unroll
        for (int j = 0; j < 4; j++) {
            int n = n0 + tx * 4 + j;
            if (n < Nn) {
                float v = acc[i][j] + bias[n];
                if (EPI == 1) v = 0.5f * v * (1.f + erff(v * 0.70710678118654752f));
                if (EPI == 2) v += Add[(size_t)m * Nn + n];
                Out[(size_t)m * Nn + n] = v;
            }
        }
    }
}

// ---------------- DCNv4 sampling: one warp per (token, group) -------------
__global__ void dcn_kernel(const float* __restrict__ val,
                           const float* __restrict__ om,
                           float* __restrict__ outp)
{
    int wg = (blockIdx.x * blockDim.x + threadIdx.x) >> 5;
    if (wg >= NTOK * GG) return;
    int lane = threadIdx.x & 31;
    int n = wg / GG;
    int g = wg % GG;
    int b  = n / HWW;
    int hw = n % HWW;
    int ii = hw / WW;
    int jj = hw % WW;

    const float* omb = om + (size_t)n * OMC + g * 27;
    const float* vb  = val + (size_t)b * HWW * CC + g * GCH + lane;

    float acc = 0.f;
#pragma unroll
    for (int k = 0; k < KK2; k++) {
        float dx = __ldg(&omb[2 * k]);
        float dy = __ldg(&omb[2 * k + 1]);
        float mk = __ldg(&omb[18 + k]);
        float px = (float)jj + (float)(k % 3 - 1) + dx;
        float py = (float)ii + (float)(k / 3 - 1) + dy;
        float x0f = floorf(px), y0f = floorf(py);
        float tx = px - x0f, ty = py - y0f;
        int x0 = (int)x0f, y0 = (int)y0f;
        int x1 = x0 + 1,   y1 = y0 + 1;

        bool vx0 = (x0 >= 0) & (x0 < WW);
        bool vx1 = (x1 >= 0) & (x1 < WW);
        bool vy0 = (y0 >= 0) & (y0 < HH);
        bool vy1 = (y1 >= 0) & (y1 < HH);

        float v00 = (vy0 && vx0) ? vb[(size_t)(y0 * WW + x0) * CC] : 0.f;
        float v01 = (vy0 && vx1) ? vb[(size_t)(y0 * WW + x1) * CC] : 0.f;
        float v10 = (vy1 && vx0) ? vb[(size_t)(y1 * WW + x0) * CC] : 0.f;
        float v11 = (vy1 && vx1) ? vb[(size_t)(y1 * WW + x1) * CC] : 0.f;

        float top = v00 * (1.f - tx) + v01 * tx;
        float bot = v10 * (1.f - tx) + v11 * tx;
        acc += mk * (top * (1.f - ty) + bot * ty);
    }
    outp[(size_t)n * CC + g * GCH + lane] = acc;
}

// ---------------- final: fin (N,C) -> out (B,C,H,W) -----------------------
__global__ void transpose_out(const float* __restrict__ fin,
                              float* __restrict__ outp)
{
    __shared__ float s[32][33];
    int b   = blockIdx.z;
    int hw0 = blockIdx.x * 32;
    int c0  = blockIdx.y * 32;
    int tx = threadIdx.x, ty = threadIdx.y;

#pragma unroll
    for (int r = 0; r < 4; r++) {
        int hw = hw0 + ty + 8 * r;
        s[ty + 8 * r][tx] = fin[(size_t)(b * HWW + hw) * CC + c0 + tx];
    }
    __syncthreads();
#pragma unroll
    for (int r = 0; r < 4; r++) {
        int c = c0 + ty + 8 * r;
        outp[(size_t)(b * CC + c) * HWW + hw0 + tx] = s[tx][ty + 8 * r];
    }
}

// --------------------------------------------------------------------------
extern "C" void kernel_launch(void* const* d_in, const int* in_sizes, int n_in,
                              void* d_out, int out_size)
{
    const float* x       = (const float*)d_in[0];
    const float* ln1_g   = (const float*)d_in[1];
    const float* ln1_b   = (const float*)d_in[2];
    const float* vproj_w = (const float*)d_in[3];
    const float* vproj_b = (const float*)d_in[4];
    const float* om_w    = (const float*)d_in[5];
    const float* om_b    = (const float*)d_in[6];
    const float* oproj_w = (const float*)d_in[7];
    const float* oproj_b = (const float*)d_in[8];
    const float* ln2_g   = (const float*)d_in[9];
    const float* ln2_b   = (const float*)d_in[10];
    const float* fc1_w   = (const float*)d_in[11];
    const float* fc1_b   = (const float*)d_in[12];
    const float* fc2_w   = (const float*)d_in[13];
    const float* fc2_b   = (const float*)d_in[14];
    float* outp = (float*)d_out;

    float *xp, *tn, *val, *om, *dcn, *res, *ln2o, *hid, *fin;
    cudaGetSymbolAddress((void**)&xp,  g_xp);
    cudaGetSymbolAddress((void**)&tn,  g_tn);
    cudaGetSymbolAddress((void**)&val, g_val);
    cudaGetSymbolAddress((void**)&om,  g_om);
    cudaGetSymbolAddress((void**)&dcn, g_dcn);
    cudaGetSymbolAddress((void**)&res, g_res);
    cudaGetSymbolAddress((void**)&ln2o, g_ln2);
    cudaGetSymbolAddress((void**)&hid, g_hid);
    cudaGetSymbolAddress((void**)&fin, g_fin);

    // 1. transpose + LN1
    ln1_kernel<<<NTOK / 8, 256>>>(x, ln1_g, ln1_b, xp, tn);

    // 2. val = tn @ vproj_w + b
    gemm_k<0><<<dim3(NTOK / 64, 6), 256>>>(tn, vproj_w, vproj_b, nullptr, val,
                                           NTOK, CC, CC);
    // 3. om = tn @ om_w + b   (Nn = 324)
    gemm_k<0><<<dim3(NTOK / 64, 6), 256>>>(tn, om_w, om_b, nullptr, om,
                                           NTOK, OMC, CC);
    // 4. DCN sampling
    dcn_kernel<<<(NTOK * GG) / 8, 256>>>(val, om, dcn);

    // 5. res = xp + dcn @ oproj_w + b
    gemm_k<2><<<dim3(NTOK / 64, 6), 256>>>(dcn, oproj_w, oproj_b, xp, res,
                                           NTOK, CC, CC);
    // 6. LN2
    ln2_kernel<<<NTOK / 8, 256>>>(res, ln2_g, ln2_b, ln2o);

    // 7. hid = gelu(ln2o @ fc1_w + b)
    gemm_k<1><<<dim3(NTOK / 64, HID / 64), 256>>>(ln2o, fc1_w, fc1_b, nullptr,
                                                  hid, NTOK, HID, CC);
    // 8. fin = res + hid @ fc2_w + b
    gemm_k<2><<<dim3(NTOK / 64, 6), 256>>>(hid, fc2_w, fc2_b, res, fin,
                                           NTOK, CC, HID);
    // 9. transpose back to (B,C,H,W)
    transpose_out<<<dim3(HWW / 32, CC / 32, BB), dim3(32, 8)>>>(fin, outp);
}

// round 3
// speedup vs baseline: 2.4196x; 2.4196x over previous
#include <cuda_runtime.h>
#include <math.h>
#include <stdint.h>

#define BB   4
#define CC   384
#define HH   56
#define WW   56
#define HWW  3136
#define NTOK 12544
#define GG   12
#define GCH  32
#define KK2  9
#define OMC  324
#define HID  1536
#define EPSV 1e-5f

// ---------------- scratch (device globals; no allocation) ----------------
__device__ float g_xp [NTOK * CC];
__device__ float g_tn [NTOK * CC];
__device__ float g_val[NTOK * CC];
__device__ float g_om [NTOK * OMC];
__device__ float g_dcn[NTOK * CC];
__device__ float g_res[NTOK * CC];
__device__ float g_ln2[NTOK * CC];
__device__ float g_hid[NTOK * HID];
__device__ float g_fin[NTOK * CC];
// transposed weights [N,K] row-major (B in col-major form for mma row.col)
__device__ float g_wv [CC * CC];
__device__ float g_wo [CC * CC];
__device__ float g_w1 [HID * CC];
__device__ float g_w2 [CC * HID];
__device__ float g_wm [CC * CC];   // om_w^T, rows >= 324 stay zero

// ===================== mma.sync tf32 GEMM =====================
// Out[M,Nn] = A[M,K] @ Wt[Nn,K]^T ; out stride = Nn.
// EPI: 0 = +bias ; 1 = +bias+GELU ; 2 = +bias+Add
__device__ __forceinline__ uint32_t f2tf32(float f) {
    uint32_t u;
    asm("cvt.rna.tf32.f32 %0, %1;" : "=r"(u) : "f"(f));
    return u;
}

#define MMA_TF32(d, a, b) \
    asm volatile("mma.sync.aligned.m16n8k8.row.col.f32.tf32.tf32.f32 " \
        "{%0,%1,%2,%3}, {%4,%5,%6,%7}, {%8,%9}, {%0,%1,%2,%3};" \
        : "+f"((d)[0]), "+f"((d)[1]), "+f"((d)[2]), "+f"((d)[3]) \
        : "r"((a)[0]), "r"((a)[1]), "r"((a)[2]), "r"((a)[3]), \
          "r"((b)[0]), "r"((b)[1]))

#define KCH 16

template <int EPI>
__global__ __launch_bounds__(256, 2) void gemm_mma(
    const float* __restrict__ A, const float* __restrict__ Wt,
    const float* __restrict__ bias, const float* __restrict__ Add,
    float* __restrict__ Out, int Nn, int K)
{
    __shared__ uint32_t As[2][KCH][136];
    __shared__ uint32_t Bs[2][KCH][136];

    const int tid  = threadIdx.x;
    const int lane = tid & 31, warp = tid >> 5;
    const int wm = (warp >> 2) * 64, wn = (warp & 3) * 32;
    const int g4 = lane >> 2, tg = lane & 3;
    const int m0 = blockIdx.x * 128, n0 = blockIdx.y * 128;

    const int r  = tid >> 2;   // 0..63 (row within half-tile)
    const int kq = tid & 3;    // float4 index within 16-wide k chunk

    float acc[4][4][4];
#pragma unroll
    for (int a = 0; a < 4; a++)
#pragma unroll
        for (int b = 0; b < 4; b++)
#pragma unroll
            for (int c = 0; c < 4; c++) acc[a][b][c] = 0.f;

    uint32_t va[2][4], vb[2][4];
    const int nkc = K >> 4;

    // prologue: load + store chunk 0
    {
        const int k0 = 0;
#pragma unroll
        for (int i = 0; i < 2; i++) {
            int rr = r + 64 * i;
            float4 fa = *reinterpret_cast<const float4*>(A  + (size_t)(m0 + rr) * K + k0 + kq * 4);
            float4 fb = *reinterpret_cast<const float4*>(Wt + (size_t)(n0 + rr) * K + k0 + kq * 4);
            va[i][0] = f2tf32(fa.x); va[i][1] = f2tf32(fa.y);
            va[i][2] = f2tf32(fa.z); va[i][3] = f2tf32(fa.w);
            vb[i][0] = f2tf32(fb.x); vb[i][1] = f2tf32(fb.y);
            vb[i][2] = f2tf32(fb.z); vb[i][3] = f2tf32(fb.w);
        }
#pragma unroll
        for (int i = 0; i < 2; i++) {
            int ms = (r + 64 * i) ^ (kq << 3);
#pragma unroll
            for (int j = 0; j < 4; j++) {
                As[0][kq * 4 + j][ms] = va[i][j];
                Bs[0][kq * 4 + j][ms] = vb[i][j];
            }
        }
    }
    __syncthreads();

    for (int kc = 0; kc < nkc; kc++) {
        const int buf = kc & 1;
        if (kc + 1 < nkc) {
            const int k0 = (kc + 1) << 4;
#pragma unroll
            for (int i = 0; i < 2; i++) {
                int rr = r + 64 * i;
                float4 fa = *reinterpret_cast<const float4*>(A  + (size_t)(m0 + rr) * K + k0 + kq * 4);
                float4 fb = *reinterpret_cast<const float4*>(Wt + (size_t)(n0 + rr) * K + k0 + kq * 4);
                va[i][0] = f2tf32(fa.x); va[i][1] = f2tf32(fa.y);
                va[i][2] = f2tf32(fa.z); va[i][3] = f2tf32(fa.w);
                vb[i][0] = f2tf32(fb.x); vb[i][1] = f2tf32(fb.y);
                vb[i][2] = f2tf32(fb.z); vb[i][3] = f2tf32(fb.w);
            }
        }

        // compute on buf
#pragma unroll
        for (int s = 0; s < 2; s++) {
            const int ko = s * 8;
            const int ka = ko + tg, kb = ka + 4;
            const int swa = (ka >> 2) << 3, swb = (kb >> 2) << 3;
            uint32_t af[4][4], bf[4][2];
#pragma unroll
            for (int mt = 0; mt < 4; mt++) {
                int m = wm + mt * 16 + g4;
                af[mt][0] = As[buf][ka][m ^ swa];
                af[mt][1] = As[buf][ka][(m + 8) ^ swa];
                af[mt][2] = As[buf][kb][m ^ swb];
                af[mt][3] = As[buf][kb][(m + 8) ^ swb];
            }
#pragma unroll
            for (int nt = 0; nt < 4; nt++) {
                int n = wn + nt * 8 + g4;
                bf[nt][0] = Bs[buf][ka][n ^ swa];
                bf[nt][1] = Bs[buf][kb][n ^ swb];
            }
#pragma unroll
            for (int mt = 0; mt < 4; mt++)
#pragma unroll
                for (int nt = 0; nt < 4; nt++)
                    MMA_TF32(acc[mt][nt], af[mt], bf[nt]);
        }

        if (kc + 1 < nkc) {
            const int nb = (kc + 1) & 1;
            __syncthreads();
#pragma unroll
            for (int i = 0; i < 2; i++) {
                int ms = (r + 64 * i) ^ (kq << 3);
#pragma unroll
                for (int j = 0; j < 4; j++) {
                    As[nb][kq * 4 + j][ms] = va[i][j];
                    Bs[nb][kq * 4 + j][ms] = vb[i][j];
                }
            }
            __syncthreads();
        }
    }

    // epilogue
#pragma unroll
    for (int mt = 0; mt < 4; mt++) {
        int row = m0 + wm + mt * 16 + g4;
#pragma unroll
        for (int nt = 0; nt < 4; nt++) {
            int col = n0 + wn + nt * 8 + tg * 2;
            if (col < Nn) {
                float b0 = __ldg(&bias[col]), b1 = __ldg(&bias[col + 1]);
                float v0 = acc[mt][nt][0] + b0;
                float v1 = acc[mt][nt][1] + b1;
                float v2 = acc[mt][nt][2] + b0;
                float v3 = acc[mt][nt][3] + b1;
                if (EPI == 1) {
                    v0 = 0.5f * v0 * (1.f + erff(v0 * 0.70710678118654752f));
                    v1 = 0.5f * v1 * (1.f + erff(v1 * 0.70710678118654752f));
                    v2 = 0.5f * v2 * (1.f + erff(v2 * 0.70710678118654752f));
                    v3 = 0.5f * v3 * (1.f + erff(v3 * 0.70710678118654752f));
                }
                if (EPI == 2) {
                    v0 += Add[(size_t)row * Nn + col];
                    v1 += Add[(size_t)row * Nn + col + 1];
                    v2 += Add[(size_t)(row + 8) * Nn + col];
                    v3 += Add[(size_t)(row + 8) * Nn + col + 1];
                }
                *reinterpret_cast<float2*>(Out + (size_t)row * Nn + col)       = make_float2(v0, v1);
                *reinterpret_cast<float2*>(Out + (size_t)(row + 8) * Nn + col) = make_float2(v2, v3);
            }
        }
    }
}

// ---------------- guarded weight transpose: src[K,N] -> dst[N,K] ----------
__global__ void transpose_w(const float* __restrict__ src, float* __restrict__ dst,
                            int Kdim, int Ndim)
{
    __shared__ float s[32][33];
    int n0 = blockIdx.x * 32, k0 = blockIdx.y * 32;
    int tx = threadIdx.x, ty = threadIdx.y;
#pragma unroll
    for (int r = 0; r < 4; r++) {
        int k = k0 + ty + 8 * r, n = n0 + tx;
        s[ty + 8 * r][tx] = (k < Kdim && n < Ndim) ? src[(size_t)k * Ndim + n] : 0.f;
    }
    __syncthreads();
#pragma unroll
    for (int r = 0; r < 4; r++) {
        int n = n0 + ty + 8 * r, k = k0 + tx;
        if (n < Ndim && k < Kdim)
            dst[(size_t)n * Kdim + k] = s[tx][ty + 8 * r];
    }
}

// ---------------- LN1: transpose x + layernorm ----------------
__global__ void ln1_kernel(const float* __restrict__ x,
                           const float* __restrict__ gam,
                           const float* __restrict__ bet,
                           float* __restrict__ xp, float* __restrict__ tn)
{
    int warp = (blockIdx.x * blockDim.x + threadIdx.x) >> 5;
    if (warp >= NTOK) return;
    int lane = threadIdx.x & 31;
    int b  = warp / HWW;
    int hw = warp % HWW;
    const float* xb = x + (size_t)b * CC * HWW + hw;

    float v[12];
#pragma unroll
    for (int i = 0; i < 12; i++) v[i] = xb[(size_t)(lane + 32 * i) * HWW];
    float s = 0.f;
#pragma unroll
    for (int i = 0; i < 12; i++) s += v[i];
#pragma unroll
    for (int o = 16; o; o >>= 1) s += __shfl_xor_sync(0xffffffffu, s, o);
    float mu = s * (1.0f / CC);
    float q = 0.f;
#pragma unroll
    for (int i = 0; i < 12; i++) { float d = v[i] - mu; q += d * d; }
#pragma unroll
    for (int o = 16; o; o >>= 1) q += __shfl_xor_sync(0xffffffffu, q, o);
    float rs = rsqrtf(q * (1.0f / CC) + EPSV);
    size_t base = (size_t)warp * CC;
#pragma unroll
    for (int i = 0; i < 12; i++) {
        int c = lane + 32 * i;
        xp[base + c] = v[i];
        tn[base + c] = (v[i] - mu) * rs * gam[c] + bet[c];
    }
}

__global__ void ln2_kernel(const float* __restrict__ res,
                           const float* __restrict__ gam,
                           const float* __restrict__ bet,
                           float* __restrict__ outp)
{
    int warp = (blockIdx.x * blockDim.x + threadIdx.x) >> 5;
    if (warp >= NTOK) return;
    int lane = threadIdx.x & 31;
    size_t base = (size_t)warp * CC;
    float v[12];
#pragma unroll
    for (int i = 0; i < 12; i++) v[i] = res[base + lane + 32 * i];
    float s = 0.f;
#pragma unroll
    for (int i = 0; i < 12; i++) s += v[i];
#pragma unroll
    for (int o = 16; o; o >>= 1) s += __shfl_xor_sync(0xffffffffu, s, o);
    float mu = s * (1.0f / CC);
    float q = 0.f;
#pragma unroll
    for (int i = 0; i < 12; i++) { float d = v[i] - mu; q += d * d; }
#pragma unroll
    for (int o = 16; o; o >>= 1) q += __shfl_xor_sync(0xffffffffu, q, o);
    float rs = rsqrtf(q * (1.0f / CC) + EPSV);
#pragma unroll
    for (int i = 0; i < 12; i++) {
        int c = lane + 32 * i;
        outp[base + c] = (v[i] - mu) * rs * gam[c] + bet[c];
    }
}

// ---------------- DCNv4 sampling ----------------
__global__ void dcn_kernel(const float* __restrict__ val,
                           const float* __restrict__ om,
                           float* __restrict__ outp)
{
    int wg = (blockIdx.x * blockDim.x + threadIdx.x) >> 5;
    if (wg >= NTOK * GG) return;
    int lane = threadIdx.x & 31;
    int n = wg / GG;
    int g = wg % GG;
    int b  = n / HWW;
    int hw = n % HWW;
    int ii = hw / WW;
    int jj = hw % WW;

    const float* omb = om + (size_t)n * OMC + g * 27;
    const float* vb  = val + (size_t)b * HWW * CC + g * GCH + lane;

    float acc = 0.f;
#pragma unroll
    for (int k = 0; k < KK2; k++) {
        float dx = __ldg(&omb[2 * k]);
        float dy = __ldg(&omb[2 * k + 1]);
        float mk = __ldg(&omb[18 + k]);
        float px = (float)jj + (float)(k % 3 - 1) + dx;
        float py = (float)ii + (float)(k / 3 - 1) + dy;
        float x0f = floorf(px), y0f = floorf(py);
        float tx = px - x0f, ty = py - y0f;
        int x0 = (int)x0f, y0 = (int)y0f;
        int x1 = x0 + 1,   y1 = y0 + 1;
        bool vx0 = (x0 >= 0) & (x0 < WW);
        bool vx1 = (x1 >= 0) & (x1 < WW);
        bool vy0 = (y0 >= 0) & (y0 < HH);
        bool vy1 = (y1 >= 0) & (y1 < HH);
        float v00 = (vy0 && vx0) ? vb[(size_t)(y0 * WW + x0) * CC] : 0.f;
        float v01 = (vy0 && vx1) ? vb[(size_t)(y0 * WW + x1) * CC] : 0.f;
        float v10 = (vy1 && vx0) ? vb[(size_t)(y1 * WW + x0) * CC] : 0.f;
        float v11 = (vy1 && vx1) ? vb[(size_t)(y1 * WW + x1) * CC] : 0.f;
        float top = v00 * (1.f - tx) + v01 * tx;
        float bot = v10 * (1.f - tx) + v11 * tx;
        acc += mk * (top * (1.f - ty) + bot * ty);
    }
    outp[(size_t)n * CC + g * GCH + lane] = acc;
}

// ---------------- final transpose ----------------
__global__ void transpose_out(const float* __restrict__ fin,
                              float* __restrict__ outp)
{
    __shared__ float s[32][33];
    int b   = blockIdx.z;
    int hw0 = blockIdx.x * 32;
    int c0  = blockIdx.y * 32;
    int tx = threadIdx.x, ty = threadIdx.y;
#pragma unroll
    for (int r = 0; r < 4; r++) {
        int hw = hw0 + ty + 8 * r;
        s[ty + 8 * r][tx] = fin[(size_t)(b * HWW + hw) * CC + c0 + tx];
    }
    __syncthreads();
#pragma unroll
    for (int r = 0; r < 4; r++) {
        int c = c0 + ty + 8 * r;
        outp[(size_t)(b * CC + c) * HWW + hw0 + tx] = s[tx][ty + 8 * r];
    }
}

// --------------------------------------------------------------------------
extern "C" void kernel_launch(void* const* d_in, const int* in_sizes, int n_in,
                              void* d_out, int out_size)
{
    const float* x       = (const float*)d_in[0];
    const float* ln1_g   = (const float*)d_in[1];
    const float* ln1_b   = (const float*)d_in[2];
    const float* vproj_w = (const float*)d_in[3];
    const float* vproj_b = (const float*)d_in[4];
    const float* om_w    = (const float*)d_in[5];
    const float* om_b    = (const float*)d_in[6];
    const float* oproj_w = (const float*)d_in[7];
    const float* oproj_b = (const float*)d_in[8];
    const float* ln2_g   = (const float*)d_in[9];
    const float* ln2_b   = (const float*)d_in[10];
    const float* fc1_w   = (const float*)d_in[11];
    const float* fc1_b   = (const float*)d_in[12];
    const float* fc2_w   = (const float*)d_in[13];
    const float* fc2_b   = (const float*)d_in[14];
    float* outp = (float*)d_out;

    float *xp, *tn, *val, *om, *dcn, *res, *ln2o, *hid, *fin;
    float *wv, *wo, *w1, *w2, *wm;
    cudaGetSymbolAddress((void**)&xp,  g_xp);
    cudaGetSymbolAddress((void**)&tn,  g_tn);
    cudaGetSymbolAddress((void**)&val, g_val);
    cudaGetSymbolAddress((void**)&om,  g_om);
    cudaGetSymbolAddress((void**)&dcn, g_dcn);
    cudaGetSymbolAddress((void**)&res, g_res);
    cudaGetSymbolAddress((void**)&ln2o, g_ln2);
    cudaGetSymbolAddress((void**)&hid, g_hid);
    cudaGetSymbolAddress((void**)&fin, g_fin);
    cudaGetSymbolAddress((void**)&wv,  g_wv);
    cudaGetSymbolAddress((void**)&wo,  g_wo);
    cudaGetSymbolAddress((void**)&w1,  g_w1);
    cudaGetSymbolAddress((void**)&w2,  g_w2);
    cudaGetSymbolAddress((void**)&wm,  g_wm);

    dim3 tb(32, 8);
    // weight transposes: [K,N] -> [N,K]
    transpose_w<<<dim3(CC / 32, CC / 32), tb>>>(vproj_w, wv, CC, CC);
    transpose_w<<<dim3(HID / 32, CC / 32), tb>>>(fc1_w, w1, CC, HID);
    transpose_w<<<dim3(CC / 32, CC / 32), tb>>>(oproj_w, wo, CC, CC);
    transpose_w<<<dim3(CC / 32, HID / 32), tb>>>(fc2_w, w2, HID, CC);
    transpose_w<<<dim3((OMC + 31) / 32, CC / 32), tb>>>(om_w, wm, CC, OMC);

    // 1. transpose + LN1
    ln1_kernel<<<NTOK / 8, 256>>>(x, ln1_g, ln1_b, xp, tn);

    // 2. val = tn @ vproj_w + b
    gemm_mma<0><<<dim3(NTOK / 128, 3), 256>>>(tn, wv, vproj_b, nullptr, val, CC, CC);
    // 3. om = tn @ om_w + b   (Nn = 324, padded weight rows are zero)
    gemm_mma<0><<<dim3(NTOK / 128, 3), 256>>>(tn, wm, om_b, nullptr, om, OMC, CC);
    // 4. DCN sampling
    dcn_kernel<<<(NTOK * GG) / 8, 256>>>(val, om, dcn);
    // 5. res = xp + dcn @ oproj_w + b
    gemm_mma<2><<<dim3(NTOK / 128, 3), 256>>>(dcn, wo, oproj_b, xp, res, CC, CC);
    // 6. LN2
    ln2_kernel<<<NTOK / 8, 256>>>(res, ln2_g, ln2_b, ln2o);
    // 7. hid = gelu(ln2o @ fc1_w + b)
    gemm_mma<1><<<dim3(NTOK / 128, HID / 128), 256>>>(ln2o, w1, fc1_b, nullptr, hid, HID, CC);
    // 8. fin = res + hid @ fc2_w + b
    gemm_mma<2><<<dim3(NTOK / 128, 3), 256>>>(hid, w2, fc2_b, res, fin, CC, HID);
    // 9. transpose back
    transpose_out<<<dim3(HWW / 32, CC / 32, BB), tb>>>(fin, outp);
}

// round 4
// speedup vs baseline: 2.5802x; 1.0664x over previous
#include <cuda_runtime.h>
#include <math.h>
#include <stdint.h>

#define BB   4
#define CC   384
#define HH   56
#define WW   56
#define HWW  3136
#define NTOK 12544
#define GG   12
#define GCH  32
#define KK2  9
#define OMC  324
#define HID  1536
#define EPSV 1e-5f

// ---------------- scratch (device globals; no allocation) ----------------
__device__ float g_xp [NTOK * CC];
__device__ float g_tn [NTOK * CC];
__device__ float g_val[NTOK * CC];
__device__ float g_om [NTOK * OMC];
__device__ float g_dcn[NTOK * CC];
__device__ float g_res[NTOK * CC];
__device__ float g_ln2[NTOK * CC];
__device__ float g_hid[NTOK * HID];
__device__ float g_fin[NTOK * CC];
// transposed weights [N,K] row-major
__device__ float g_wv [CC * CC];
__device__ float g_wo [CC * CC];
__device__ float g_w1 [HID * CC];
__device__ float g_w2 [CC * HID];
__device__ float g_wm [CC * CC];   // om_w^T, rows >= 324 stay zero

// ===================== helpers =====================
__device__ __forceinline__ uint32_t smem_u32(const void* p) {
    uint32_t a;
    asm("{ .reg .u64 t; cvta.to.shared.u64 t, %1; cvt.u32.u64 %0, t; }"
        : "=r"(a) : "l"(p));
    return a;
}
#define CP16(dst, src) \
    asm volatile("cp.async.ca.shared.global [%0], [%1], 16;" \
                 :: "r"(dst), "l"(src))
#define CP_COMMIT() asm volatile("cp.async.commit_group;")
#define CP_WAIT0()  asm volatile("cp.async.wait_group 0;")

#define MMA_TF32(d, a, b) \
    asm volatile("mma.sync.aligned.m16n8k8.row.col.f32.tf32.tf32.f32 " \
        "{%0,%1,%2,%3}, {%4,%5,%6,%7}, {%8,%9}, {%0,%1,%2,%3};" \
        : "+f"((d)[0]), "+f"((d)[1]), "+f"((d)[2]), "+f"((d)[3]) \
        : "r"((a)[0]), "r"((a)[1]), "r"((a)[2]), "r"((a)[3]), \
          "r"((b)[0]), "r"((b)[1]))

// ===================== mma.sync tf32 GEMM (cp.async pipeline) =============
// Out[M,Nn] = A[M,K] @ Wt[Nn,K]^T ; tile 128x128, K chunk 16, 2-stage.
// EPI: 0 = +bias ; 1 = +bias+GELU ; 2 = +bias+Add
#define SSTR 20   // smem row stride in words (conflict-free: 20*g4+tg spans all banks)

template <int EPI>
__global__ __launch_bounds__(256, 2) void gemm_mma(
    const float* __restrict__ A, const float* __restrict__ Wt,
    const float* __restrict__ bias, const float* __restrict__ Add,
    float* __restrict__ Out, int Nn, int K)
{
    __shared__ float As[2][128][SSTR];
    __shared__ float Bs[2][128][SSTR];

    const int tid  = threadIdx.x;
    const int lane = tid & 31, warp = tid >> 5;
    const int wm = (warp >> 2) * 64, wn = (warp & 3) * 32;
    const int g4 = lane >> 2, tg = lane & 3;
    const int m0 = blockIdx.x * 128, n0 = blockIdx.y * 128;
    const int r  = tid >> 2;   // 0..63
    const int kq = tid & 3;    // 16B slot within 16-wide k chunk

    float acc[4][4][4];
#pragma unroll
    for (int a = 0; a < 4; a++)
#pragma unroll
        for (int b = 0; b < 4; b++)
#pragma unroll
            for (int c = 0; c < 4; c++) acc[a][b][c] = 0.f;

    const int nkc = K >> 4;

    const float* srcA0 = A  + (size_t)(m0 + r) * K + kq * 4;
    const float* srcA1 = A  + (size_t)(m0 + r + 64) * K + kq * 4;
    const float* srcB0 = Wt + (size_t)(n0 + r) * K + kq * 4;
    const float* srcB1 = Wt + (size_t)(n0 + r + 64) * K + kq * 4;

#define ISSUE(kc, buf) do {                                           \
        int _k0 = (kc) << 4;                                          \
        CP16(smem_u32(&As[buf][r][kq * 4]),      srcA0 + _k0);        \
        CP16(smem_u32(&As[buf][r + 64][kq * 4]), srcA1 + _k0);        \
        CP16(smem_u32(&Bs[buf][r][kq * 4]),      srcB0 + _k0);        \
        CP16(smem_u32(&Bs[buf][r + 64][kq * 4]), srcB1 + _k0);        \
        CP_COMMIT();                                                  \
    } while (0)

    ISSUE(0, 0);

    for (int kc = 0; kc < nkc; kc++) {
        const int buf = kc & 1;
        CP_WAIT0();
        __syncthreads();
        if (kc + 1 < nkc) ISSUE(kc + 1, buf ^ 1);

#pragma unroll
        for (int s = 0; s < 2; s++) {
            const int ka = s * 8 + tg, kb = ka + 4;
            uint32_t af[4][4], bf[4][2];
#pragma unroll
            for (int mt = 0; mt < 4; mt++) {
                int m = wm + mt * 16 + g4;
                af[mt][0] = __float_as_uint(As[buf][m][ka]);
                af[mt][1] = __float_as_uint(As[buf][m + 8][ka]);
                af[mt][2] = __float_as_uint(As[buf][m][kb]);
                af[mt][3] = __float_as_uint(As[buf][m + 8][kb]);
            }
#pragma unroll
            for (int nt = 0; nt < 4; nt++) {
                int n = wn + nt * 8 + g4;
                bf[nt][0] = __float_as_uint(Bs[buf][n][ka]);
                bf[nt][1] = __float_as_uint(Bs[buf][n][kb]);
            }
#pragma unroll
            for (int mt = 0; mt < 4; mt++)
#pragma unroll
                for (int nt = 0; nt < 4; nt++)
                    MMA_TF32(acc[mt][nt], af[mt], bf[nt]);
        }
    }
#undef ISSUE

    // epilogue
#pragma unroll
    for (int mt = 0; mt < 4; mt++) {
        int row = m0 + wm + mt * 16 + g4;
#pragma unroll
        for (int nt = 0; nt < 4; nt++) {
            int col = n0 + wn + nt * 8 + tg * 2;
            if (col < Nn) {
                float b0 = __ldg(&bias[col]), b1 = __ldg(&bias[col + 1]);
                float v0 = acc[mt][nt][0] + b0;
                float v1 = acc[mt][nt][1] + b1;
                float v2 = acc[mt][nt][2] + b0;
                float v3 = acc[mt][nt][3] + b1;
                if (EPI == 1) {
                    v0 = 0.5f * v0 * (1.f + erff(v0 * 0.70710678118654752f));
                    v1 = 0.5f * v1 * (1.f + erff(v1 * 0.70710678118654752f));
                    v2 = 0.5f * v2 * (1.f + erff(v2 * 0.70710678118654752f));
                    v3 = 0.5f * v3 * (1.f + erff(v3 * 0.70710678118654752f));
                }
                if (EPI == 2) {
                    v0 += Add[(size_t)row * Nn + col];
                    v1 += Add[(size_t)row * Nn + col + 1];
                    v2 += Add[(size_t)(row + 8) * Nn + col];
                    v3 += Add[(size_t)(row + 8) * Nn + col + 1];
                }
                *reinterpret_cast<float2*>(Out + (size_t)row * Nn + col)       = make_float2(v0, v1);
                *reinterpret_cast<float2*>(Out + (size_t)(row + 8) * Nn + col) = make_float2(v2, v3);
            }
        }
    }
}

// ---------------- guarded weight transpose: src[K,N] -> dst[N,K] ----------
__global__ void transpose_w(const float* __restrict__ src, float* __restrict__ dst,
                            int Kdim, int Ndim)
{
    __shared__ float s[32][33];
    int n0 = blockIdx.x * 32, k0 = blockIdx.y * 32;
    int tx = threadIdx.x, ty = threadIdx.y;
#pragma unroll
    for (int r = 0; r < 4; r++) {
        int k = k0 + ty + 8 * r, n = n0 + tx;
        s[ty + 8 * r][tx] = (k < Kdim && n < Ndim) ? src[(size_t)k * Ndim + n] : 0.f;
    }
    __syncthreads();
#pragma unroll
    for (int r = 0; r < 4; r++) {
        int n = n0 + ty + 8 * r, k = k0 + tx;
        if (n < Ndim && k < Kdim)
            dst[(size_t)n * Kdim + k] = s[tx][ty + 8 * r];
    }
}

// ---------------- LN1: transpose x + layernorm ----------------
__global__ void ln1_kernel(const float* __restrict__ x,
                           const float* __restrict__ gam,
                           const float* __restrict__ bet,
                           float* __restrict__ xp, float* __restrict__ tn)
{
    int warp = (blockIdx.x * blockDim.x + threadIdx.x) >> 5;
    if (warp >= NTOK) return;
    int lane = threadIdx.x & 31;
    int b  = warp / HWW;
    int hw = warp - b * HWW;
    const float* xb = x + (size_t)b * CC * HWW + hw;

    float v[12];
#pragma unroll
    for (int i = 0; i < 12; i++) v[i] = xb[(size_t)(lane + 32 * i) * HWW];
    float s = 0.f;
#pragma unroll
    for (int i = 0; i < 12; i++) s += v[i];
#pragma unroll
    for (int o = 16; o; o >>= 1) s += __shfl_xor_sync(0xffffffffu, s, o);
    float mu = s * (1.0f / CC);
    float q = 0.f;
#pragma unroll
    for (int i = 0; i < 12; i++) { float d = v[i] - mu; q += d * d; }
#pragma unroll
    for (int o = 16; o; o >>= 1) q += __shfl_xor_sync(0xffffffffu, q, o);
    float rs = rsqrtf(q * (1.0f / CC) + EPSV);
    size_t base = (size_t)warp * CC;
#pragma unroll
    for (int i = 0; i < 12; i++) {
        int c = lane + 32 * i;
        xp[base + c] = v[i];
        tn[base + c] = (v[i] - mu) * rs * gam[c] + bet[c];
    }
}

__global__ void ln2_kernel(const float* __restrict__ res,
                           const float* __restrict__ gam,
                           const float* __restrict__ bet,
                           float* __restrict__ outp)
{
    int warp = (blockIdx.x * blockDim.x + threadIdx.x) >> 5;
    if (warp >= NTOK) return;
    int lane = threadIdx.x & 31;
    size_t base = (size_t)warp * CC;
    float v[12];
#pragma unroll
    for (int i = 0; i < 12; i++) v[i] = res[base + lane + 32 * i];
    float s = 0.f;
#pragma unroll
    for (int i = 0; i < 12; i++) s += v[i];
#pragma unroll
    for (int o = 16; o; o >>= 1) s += __shfl_xor_sync(0xffffffffu, s, o);
    float mu = s * (1.0f / CC);
    float q = 0.f;
#pragma unroll
    for (int i = 0; i < 12; i++) { float d = v[i] - mu; q += d * d; }
#pragma unroll
    for (int o = 16; o; o >>= 1) q += __shfl_xor_sync(0xffffffffu, q, o);
    float rs = rsqrtf(q * (1.0f / CC) + EPSV);
#pragma unroll
    for (int i = 0; i < 12; i++) {
        int c = lane + 32 * i;
        outp[base + c] = (v[i] - mu) * rs * gam[c] + bet[c];
    }
}

// ---------------- DCNv4 sampling: one block per token, warp = group -------
__global__ __launch_bounds__(384) void dcn_kernel(
    const float* __restrict__ val,
    const float* __restrict__ om,
    float* __restrict__ outp)
{
    __shared__ float s_om[OMC];
    const int n = blockIdx.x;
    const int tid = threadIdx.x;
    if (tid < OMC) s_om[tid] = om[(size_t)n * OMC + tid];
    __syncthreads();

    const int g = tid >> 5, lane = tid & 31;
    const int b = n / HWW;
    const int hw = n - b * HWW;
    const int ii = hw / WW;
    const int jj = hw - ii * WW;

    const float* omb = s_om + g * 27;
    const float* vb  = val + b * (HWW * CC) + g * GCH + lane;

    float acc = 0.f;
#pragma unroll
    for (int k = 0; k < KK2; k++) {
        float dx = omb[2 * k];
        float dy = omb[2 * k + 1];
        float mk = omb[18 + k];
        float px = (float)jj + (float)(k % 3 - 1) + dx;
        float py = (float)ii + (float)(k / 3 - 1) + dy;
        float x0f = floorf(px), y0f = floorf(py);
        float tx = px - x0f, ty = py - y0f;
        int x0 = (int)x0f, y0 = (int)y0f;
        int x1 = x0 + 1,   y1 = y0 + 1;
        bool vx0 = (x0 >= 0) & (x0 < WW);
        bool vx1 = (x1 >= 0) & (x1 < WW);
        bool vy0 = (y0 >= 0) & (y0 < HH);
        bool vy1 = (y1 >= 0) & (y1 < HH);
        int row0 = y0 * (WW * CC), row1 = row0 + WW * CC;
        float v00 = (vy0 && vx0) ? __ldg(vb + row0 + x0 * CC) : 0.f;
        float v01 = (vy0 && vx1) ? __ldg(vb + row0 + x1 * CC) : 0.f;
        float v10 = (vy1 && vx0) ? __ldg(vb + row1 + x0 * CC) : 0.f;
        float v11 = (vy1 && vx1) ? __ldg(vb + row1 + x1 * CC) : 0.f;
        float top = v00 * (1.f - tx) + v01 * tx;
        float bot = v10 * (1.f - tx) + v11 * tx;
        acc += mk * (top * (1.f - ty) + bot * ty);
    }
    outp[n * CC + g * GCH + lane] = acc;
}

// ---------------- final transpose ----------------
__global__ void transpose_out(const float* __restrict__ fin,
                              float* __restrict__ outp)
{
    __shared__ float s[32][33];
    int b   = blockIdx.z;
    int hw0 = blockIdx.x * 32;
    int c0  = blockIdx.y * 32;
    int tx = threadIdx.x, ty = threadIdx.y;
#pragma unroll
    for (int r = 0; r < 4; r++) {
        int hw = hw0 + ty + 8 * r;
        s[ty + 8 * r][tx] = fin[(size_t)(b * HWW + hw) * CC + c0 + tx];
    }
    __syncthreads();
#pragma unroll
    for (int r = 0; r < 4; r++) {
        int c = c0 + ty + 8 * r;
        outp[(size_t)(b * CC + c) * HWW + hw0 + tx] = s[tx][ty + 8 * r];
    }
}

// --------------------------------------------------------------------------
extern "C" void kernel_launch(void* const* d_in, const int* in_sizes, int n_in,
                              void* d_out, int out_size)
{
    const float* x       = (const float*)d_in[0];
    const float* ln1_g   = (const float*)d_in[1];
    const float* ln1_b   = (const float*)d_in[2];
    const float* vproj_w = (const float*)d_in[3];
    const float* vproj_b = (const float*)d_in[4];
    const float* om_w    = (const float*)d_in[5];
    const float* om_b    = (const float*)d_in[6];
    const float* oproj_w = (const float*)d_in[7];
    const float* oproj_b = (const float*)d_in[8];
    const float* ln2_g   = (const float*)d_in[9];
    const float* ln2_b   = (const float*)d_in[10];
    const float* fc1_w   = (const float*)d_in[11];
    const float* fc1_b   = (const float*)d_in[12];
    const float* fc2_w   = (const float*)d_in[13];
    const float* fc2_b   = (const float*)d_in[14];
    float* outp = (float*)d_out;

    float *xp, *tn, *val, *om, *dcn, *res, *ln2o, *hid, *fin;
    float *wv, *wo, *w1, *w2, *wm;
    cudaGetSymbolAddress((void**)&xp,  g_xp);
    cudaGetSymbolAddress((void**)&tn,  g_tn);
    cudaGetSymbolAddress((void**)&val, g_val);
    cudaGetSymbolAddress((void**)&om,  g_om);
    cudaGetSymbolAddress((void**)&dcn, g_dcn);
    cudaGetSymbolAddress((void**)&res, g_res);
    cudaGetSymbolAddress((void**)&ln2o, g_ln2);
    cudaGetSymbolAddress((void**)&hid, g_hid);
    cudaGetSymbolAddress((void**)&fin, g_fin);
    cudaGetSymbolAddress((void**)&wv,  g_wv);
    cudaGetSymbolAddress((void**)&wo,  g_wo);
    cudaGetSymbolAddress((void**)&w1,  g_w1);
    cudaGetSymbolAddress((void**)&w2,  g_w2);
    cudaGetSymbolAddress((void**)&wm,  g_wm);

    dim3 tb(32, 8);
    // weight transposes: [K,N] -> [N,K]
    transpose_w<<<dim3(CC / 32, CC / 32), tb>>>(vproj_w, wv, CC, CC);
    transpose_w<<<dim3(HID / 32, CC / 32), tb>>>(fc1_w, w1, CC, HID);
    transpose_w<<<dim3(CC / 32, CC / 32), tb>>>(oproj_w, wo, CC, CC);
    transpose_w<<<dim3(CC / 32, HID / 32), tb>>>(fc2_w, w2, HID, CC);
    transpose_w<<<dim3((OMC + 31) / 32, CC / 32), tb>>>(om_w, wm, CC, OMC);

    // 1. transpose + LN1
    ln1_kernel<<<NTOK / 8, 256>>>(x, ln1_g, ln1_b, xp, tn);
    // 2. val = tn @ vproj_w + b
    gemm_mma<0><<<dim3(NTOK / 128, 3), 256>>>(tn, wv, vproj_b, nullptr, val, CC, CC);
    // 3. om = tn @ om_w + b   (Nn = 324, padded weight rows are zero)
    gemm_mma<0><<<dim3(NTOK / 128, 3), 256>>>(tn, wm, om_b, nullptr, om, OMC, CC);
    // 4. DCN sampling
    dcn_kernel<<<NTOK, 384>>>(val, om, dcn);
    // 5. res = xp + dcn @ oproj_w + b
    gemm_mma<2><<<dim3(NTOK / 128, 3), 256>>>(dcn, wo, oproj_b, xp, res, CC, CC);
    // 6. LN2
    ln2_kernel<<<NTOK / 8, 256>>>(res, ln2_g, ln2_b, ln2o);
    // 7. hid = gelu(ln2o @ fc1_w + b)
    gemm_mma<1><<<dim3(NTOK / 128, HID / 128), 256>>>(ln2o, w1, fc1_b, nullptr, hid, HID, CC);
    // 8. fin = res + hid @ fc2_w + b
    gemm_mma<2><<<dim3(NTOK / 128, 3), 256>>>(hid, w2, fc2_b, res, fin, CC, HID);
    // 9. transpose back
    transpose_out<<<dim3(HWW / 32, CC / 32, BB), tb>>>(fin, outp);
}